// round 7
// baseline (speedup 1.0000x reference)
#include <cuda_runtime.h>
#include <cuda_bf16.h>
#include <cstdint>
#include <cstddef>

#define NROW 4096
#define DIM  512
#define R2   8192          // 2N
#define THR  409           // int(4096 * 0.1)
#define CAP  1024          // compacted candidate list capacity (fallback if exceeded)

// ---------------- device scratch (no allocations allowed) ----------------
static __device__ __nv_bfloat16 g_Zb[(size_t)R2 * DIM];   // 8 MB normalized rows (bf16)
static __device__ float g_S[(size_t)R2 * R2];             // 256 MB Gram matrix
static __device__ double g_acc;

// ================= PTX helpers (base ISA only: sm_80+) =================
__device__ __forceinline__ uint32_t smem_u32(const void* p) {
    uint32_t a;
    asm("{ .reg .u64 t; cvta.to.shared.u64 t, %1; cvt.u32.u64 %0, t; }" : "=r"(a) : "l"(p));
    return a;
}
__device__ __forceinline__ void cp_async16(uint32_t saddr, const void* gptr) {
    asm volatile("cp.async.cg.shared.global [%0], [%1], 16;\n" :: "r"(saddr), "l"(gptr));
}
__device__ __forceinline__ void cp_commit() {
    asm volatile("cp.async.commit_group;\n" ::: "memory");
}
template <int N>
__device__ __forceinline__ void cp_wait() {
    asm volatile("cp.async.wait_group %0;\n" :: "n"(N) : "memory");
}
__device__ __forceinline__ void ldm_x4(uint32_t addr, uint32_t& r0, uint32_t& r1,
                                       uint32_t& r2, uint32_t& r3) {
    asm volatile("ldmatrix.sync.aligned.m8n8.x4.shared.b16 {%0,%1,%2,%3}, [%4];\n"
                 : "=r"(r0), "=r"(r1), "=r"(r2), "=r"(r3) : "r"(addr));
}
__device__ __forceinline__ void mma_bf16(float& d0, float& d1, float& d2, float& d3,
                                         uint32_t a0, uint32_t a1, uint32_t a2, uint32_t a3,
                                         uint32_t b0, uint32_t b1) {
    asm volatile("mma.sync.aligned.m16n8k16.row.col.f32.bf16.bf16.f32 "
                 "{%0,%1,%2,%3}, {%4,%5,%6,%7}, {%8,%9}, {%0,%1,%2,%3};\n"
                 : "+f"(d0), "+f"(d1), "+f"(d2), "+f"(d3)
                 : "r"(a0), "r"(a1), "r"(a2), "r"(a3), "r"(b0), "r"(b1));
}

// ---------------- math helpers ----------------
__device__ __forceinline__ float fast_exp2x(float x) {
    float y = x * 2.885390081777927f;       // 2*log2(e)*x
    float n = rintf(y);
    float r = y - n;
    float p = 1.5403530393381609e-4f;
    p = fmaf(p, r, 1.3333558146428443e-3f);
    p = fmaf(p, r, 9.6181291076284772e-3f);
    p = fmaf(p, r, 5.5504108664821580e-2f);
    p = fmaf(p, r, 2.4022650695910071e-1f);
    p = fmaf(p, r, 6.9314718055994531e-1f);
    p = fmaf(p, r, 1.0f);
    int e = (int)n;
    float s = __int_as_float((e + 127) << 23);
    return p * s;
}
__device__ __forceinline__ unsigned f2k(float x) {
    unsigned u = __float_as_uint(x);
    return (u & 0x80000000u) ? ~u : (u | 0x80000000u);
}
__device__ __forceinline__ float k2f(unsigned k) {
    return (k & 0x80000000u) ? __uint_as_float(k ^ 0x80000000u) : __uint_as_float(~k);
}
__device__ __forceinline__ float blockReduce256(float v, float* red8) {
    int tid = threadIdx.x;
    #pragma unroll
    for (int off = 16; off; off >>= 1) v += __shfl_down_sync(0xffffffffu, v, off);
    if ((tid & 31) == 0) red8[tid >> 5] = v;
    __syncthreads();
    if (tid == 0) {
        float t = 0.f;
        #pragma unroll
        for (int w = 0; w < 8; w++) t += red8[w];
        red8[0] = t;
    }
    __syncthreads();
    float r = red8[0];
    __syncthreads();
    return r;
}

// inclusive prefix scan over hist[256] via warp shuffles; total in warpsum[7]
__device__ __forceinline__ unsigned scan256(unsigned h, unsigned* warpsum, int tid) {
    __syncthreads();                       // protect warpsum reuse
    int lane = tid & 31, w = tid >> 5;
    unsigned v = h;
    #pragma unroll
    for (int off = 1; off < 32; off <<= 1) {
        unsigned u = __shfl_up_sync(0xffffffffu, v, off);
        if (lane >= off) v += u;
    }
    if (lane == 31) warpsum[w] = v;
    __syncthreads();
    if (w == 0) {
        unsigned x = (lane < 8) ? warpsum[lane] : 0u;
        #pragma unroll
        for (int off = 1; off < 8; off <<= 1) {
            unsigned u = __shfl_up_sync(0xffffffffu, x, off);
            if (lane >= off) x += u;
        }
        if (lane < 8) warpsum[lane] = x;
    }
    __syncthreads();
    if (w > 0) v += warpsum[w - 1];
    return v;
}

// ---------------- kernel 1: row L2 normalize -> bf16 ----------------
__global__ void k_normalize(const float* __restrict__ h1, const float* __restrict__ h2) {
    int r = blockIdx.x;
    if (r == 0 && threadIdx.x == 0) g_acc = 0.0;   // stream-ordered zero for select's atomics
    const float* src = (r < NROW) ? (h1 + (size_t)r * DIM)
                                  : (h2 + (size_t)(r - NROW) * DIM);
    int tid = threadIdx.x;                 // 128 threads, 4 floats each
    float4 v = ((const float4*)src)[tid];
    float ss = v.x * v.x + v.y * v.y + v.z * v.z + v.w * v.w;
    __shared__ float red[4];
    #pragma unroll
    for (int off = 16; off; off >>= 1) ss += __shfl_down_sync(0xffffffffu, ss, off);
    if ((tid & 31) == 0) red[tid >> 5] = ss;
    __syncthreads();
    if (tid == 0) {
        float t = red[0] + red[1] + red[2] + red[3];
        red[0] = 1.0f / fmaxf(sqrtf(t), 1e-12f);
    }
    __syncthreads();
    float rinv = red[0];
    __nv_bfloat162 p0 = __floats2bfloat162_rn(v.x * rinv, v.y * rinv);
    __nv_bfloat162 p1 = __floats2bfloat162_rn(v.z * rinv, v.w * rinv);
    __nv_bfloat162* dst = (__nv_bfloat162*)(g_Zb + (size_t)r * DIM);
    dst[tid * 2]     = p0;
    dst[tid * 2 + 1] = p1;
}

// ---------------- kernel 2: S = Z Z^T via mma.sync bf16, SYMMETRIC ----------------
// Only upper-triangle 128x128 tiles (2080 of 4096); off-diagonal tiles mirror-write.
#define ROWB     80
#define TILE_AB  10240                 // 128 rows * 80B
#define STAGE_B  20480                 // A + B
#define NSTAGE   3
#define NKT      16                    // 512 / 32
#define NTILE    64
#define NBLK     (NTILE * (NTILE + 1) / 2)   // 2080

__device__ __forceinline__ void load_stage(uint32_t sBase, int stage, int kt,
                                           int bm, int bn, int tid) {
    const uint32_t st = sBase + stage * STAGE_B;
    const int k0 = kt * 32;
    #pragma unroll
    for (int i = 0; i < 4; i++) {
        int id  = tid + i * 256;           // 0..1023
        int row = (id & 511) >> 2;         // 0..127
        int c   = id & 3;                  // 16B chunk
        int grow = (id < 512) ? (bm + row) : (bn + row);
        const void* g = g_Zb + (size_t)grow * DIM + k0 + c * 8;
        uint32_t s = st + (id < 512 ? 0 : TILE_AB) + row * ROWB + c * 16;
        cp_async16(s, g);
    }
}

__global__ void __launch_bounds__(256, 2) k_gemm() {
    extern __shared__ char dsm[];
    const int tid = threadIdx.x;
    const int wid = tid >> 5, l = tid & 31;

    // triangular decode: t -> (bx >= by)
    int t = blockIdx.x;
    int bx = (int)((sqrtf(8.0f * (float)t + 1.0f) - 1.0f) * 0.5f);
    while ((bx + 1) * (bx + 2) / 2 <= t) bx++;
    while (bx * (bx + 1) / 2 > t) bx--;
    int by = t - bx * (bx + 1) / 2;        // by <= bx
    const int bm = by * 128;               // row tile
    const int bn = bx * 128;               // col tile (>= row tile)

    const int wm = (wid & 3) * 32;         // warp M offset
    const int wn = (wid >> 2) * 64;        // warp N offset
    const uint32_t sBase = smem_u32(dsm);

    float acc[2][8][4];
    #pragma unroll
    for (int mi = 0; mi < 2; mi++)
        #pragma unroll
        for (int ni = 0; ni < 8; ni++)
            #pragma unroll
            for (int q = 0; q < 4; q++) acc[mi][ni][q] = 0.f;

    load_stage(sBase, 0, 0, bm, bn, tid); cp_commit();
    load_stage(sBase, 1, 1, bm, bn, tid); cp_commit();

    const uint32_t aRow = (l & 15);
    const uint32_t aChk = (l >> 4);
    const uint32_t bRow = ((l >> 4) & 1) * 8 + (l & 7);
    const uint32_t bChk = (l >> 3) & 1;

    for (int kt = 0; kt < NKT; kt++) {
        if (kt < NKT - 2) cp_wait<1>(); else cp_wait<0>();
        __syncthreads();
        if (kt + 2 < NKT) {
            load_stage(sBase, (kt + 2) % NSTAGE, kt + 2, bm, bn, tid);
            cp_commit();
        }
        const uint32_t aB = sBase + (kt % NSTAGE) * STAGE_B + wm * ROWB;
        const uint32_t bB = sBase + (kt % NSTAGE) * STAGE_B + TILE_AB + wn * ROWB;
        #pragma unroll
        for (int ks = 0; ks < 2; ks++) {
            uint32_t a[2][4];
            #pragma unroll
            for (int mi = 0; mi < 2; mi++)
                ldm_x4(aB + (mi * 16 + aRow) * ROWB + (ks * 2 + aChk) * 16,
                       a[mi][0], a[mi][1], a[mi][2], a[mi][3]);
            uint32_t b[4][4];
            #pragma unroll
            for (int nj = 0; nj < 4; nj++)
                ldm_x4(bB + (nj * 16 + bRow) * ROWB + (ks * 2 + bChk) * 16,
                       b[nj][0], b[nj][1], b[nj][2], b[nj][3]);
            #pragma unroll
            for (int mi = 0; mi < 2; mi++)
                #pragma unroll
                for (int ni = 0; ni < 8; ni++)
                    mma_bf16(acc[mi][ni][0], acc[mi][ni][1], acc[mi][ni][2], acc[mi][ni][3],
                             a[mi][0], a[mi][1], a[mi][2], a[mi][3],
                             b[ni >> 1][(ni & 1) * 2], b[ni >> 1][(ni & 1) * 2 + 1]);
        }
        __syncthreads();
    }

    const int r0 = bm + wm + (l >> 2);
    const int c0 = bn + wn + (l & 3) * 2;
    // direct write
    #pragma unroll
    for (int mi = 0; mi < 2; mi++) {
        #pragma unroll
        for (int ni = 0; ni < 8; ni++) {
            float* p0 = g_S + (size_t)(r0 + mi * 16) * R2 + c0 + ni * 8;
            float* p1 = p0 + (size_t)8 * R2;
            p0[0] = acc[mi][ni][0]; p0[1] = acc[mi][ni][1];
            p1[0] = acc[mi][ni][2]; p1[1] = acc[mi][ni][3];
        }
    }
    // mirror write (sector-efficient scattered 4B: lanes sharing l&3 cover 8
    // consecutive columns of one mirrored row -> full 32B sectors)
    if (bx != by) {
        #pragma unroll
        for (int mi = 0; mi < 2; mi++) {
            int rA = r0 + mi * 16;
            #pragma unroll
            for (int ni = 0; ni < 8; ni++) {
                int cA = c0 + ni * 8;
                g_S[(size_t)cA       * R2 + rA    ] = acc[mi][ni][0];
                g_S[(size_t)(cA + 1) * R2 + rA    ] = acc[mi][ni][1];
                g_S[(size_t)cA       * R2 + rA + 8] = acc[mi][ni][2];
                g_S[(size_t)(cA + 1) * R2 + rA + 8] = acc[mi][ni][3];
            }
        }
    }
}

// ---------------- kernel 3: per-row trim + exp-sum ----------------
// pass-1 histogram fused with load; one scan serves both ends; boundary buckets
// compacted (CAP, exact fallback); warp-shuffle scans.
__global__ void __launch_bounds__(256) k_select() {
    const int r   = blockIdx.x;
    const int tid = threadIdx.x;
    __shared__ unsigned su[R2];           // 32 KB keys
    __shared__ unsigned hist[256];
    __shared__ unsigned listH[CAP], listL[CAP];
    __shared__ unsigned cntH, cntL;
    __shared__ float    redf[8];
    __shared__ unsigned warpsum[8];
    __shared__ unsigned s_binH, s_kH, s_binL, s_kL, s_sel, s_k;

    const float* row = g_S + (size_t)r * R2;

    if (tid == 0) { cntH = 0u; cntL = 0u; }
    hist[tid] = 0u;
    __syncthreads();

    // load + exp-sum + pass-1 histogram, one sweep
    float tot = 0.f;
    #pragma unroll
    for (int j = 0; j < 8; j++) {
        int i4 = tid + j * 256;
        float4 v = ((const float4*)row)[i4];
        tot += fast_exp2x(v.x) + fast_exp2x(v.y) + fast_exp2x(v.z) + fast_exp2x(v.w);
        unsigned k0 = f2k(v.x), k1 = f2k(v.y), k2 = f2k(v.z), k3 = f2k(v.w);
        su[i4 * 4 + 0] = k0; su[i4 * 4 + 1] = k1;
        su[i4 * 4 + 2] = k2; su[i4 * 4 + 3] = k3;
        atomicAdd(&hist[k0 >> 24], 1u); atomicAdd(&hist[k1 >> 24], 1u);
        atomicAdd(&hist[k2 >> 24], 1u); atomicAdd(&hist[k3 >> 24], 1u);
    }
    tot = blockReduce256(tot, redf);      // barrier: su + hist complete

    // pass 1: one scan -> both boundary buckets
    {
        unsigned h   = hist[tid];
        unsigned pre = scan256(h, warpsum, tid);
        unsigned total = warpsum[7];      // = R2
        unsigned ge = total - pre + h, gt = total - pre;
        if (ge >= THR && gt < THR) { s_binH = (unsigned)tid; s_kH = THR - gt; }
        unsigned le = pre, lt = pre - h;
        if (le >= THR && lt < THR) { s_binL = (unsigned)tid; s_kL = THR - lt; }
    }
    __syncthreads();
    const unsigned binH = s_binH, binL = s_binL;

    // compact boundary-bucket candidates
    for (int i = tid; i < R2; i += 256) {
        unsigned key = su[i];
        unsigned b = key >> 24;
        if (b == binH) { unsigned p = atomicAdd(&cntH, 1u); if (p < CAP) listH[p] = key; }
        if (b == binL) { unsigned p = atomicAdd(&cntL, 1u); if (p < CAP) listL[p] = key; }
    }
    __syncthreads();
    const bool fbH = (cntH > CAP), fbL = (cntL > CAP);
    const unsigned nH = fbH ? 0u : cntH, nL = fbL ? 0u : cntL;

    // ---- refine high (409th-largest) over bits 23..0 ----
    unsigned prefix = binH << 24, mask = 0xFF000000u, k = s_kH;
    #pragma unroll
    for (int pass = 1; pass < 4; pass++) {
        int shift = 24 - 8 * pass;
        __syncthreads();
        hist[tid] = 0u;
        __syncthreads();
        if (!fbH) {
            for (unsigned i = tid; i < nH; i += 256) {
                unsigned key = listH[i];
                if ((key & mask) == prefix) atomicAdd(&hist[(key >> shift) & 255u], 1u);
            }
        } else {
            for (int i = tid; i < R2; i += 256) {
                unsigned key = su[i];
                if ((key & mask) == prefix) atomicAdd(&hist[(key >> shift) & 255u], 1u);
            }
        }
        __syncthreads();
        unsigned h   = hist[tid];
        unsigned pre = scan256(h, warpsum, tid);
        unsigned total = warpsum[7];
        unsigned ge = total - pre + h, gt = total - pre;
        if (ge >= k && gt < k) { s_sel = (unsigned)tid; s_k = k - gt; }
        __syncthreads();
        prefix |= s_sel << shift;
        mask   |= 255u  << shift;
        k = s_k;
    }
    const unsigned Khi = prefix, dup_hi = k;

    // ---- refine low (409th-smallest) ----
    prefix = binL << 24; mask = 0xFF000000u; k = s_kL;
    #pragma unroll
    for (int pass = 1; pass < 4; pass++) {
        int shift = 24 - 8 * pass;
        __syncthreads();
        hist[tid] = 0u;
        __syncthreads();
        if (!fbL) {
            for (unsigned i = tid; i < nL; i += 256) {
                unsigned key = listL[i];
                if ((key & mask) == prefix) atomicAdd(&hist[(key >> shift) & 255u], 1u);
            }
        } else {
            for (int i = tid; i < R2; i += 256) {
                unsigned key = su[i];
                if ((key & mask) == prefix) atomicAdd(&hist[(key >> shift) & 255u], 1u);
            }
        }
        __syncthreads();
        unsigned h   = hist[tid];
        unsigned pre = scan256(h, warpsum, tid);
        unsigned le = pre, lt = pre - h;
        if (le >= k && lt < k) { s_sel = (unsigned)tid; s_k = k - lt; }
        __syncthreads();
        prefix |= s_sel << shift;
        mask   |= 255u  << shift;
        k = s_k;
    }
    const unsigned Klo = prefix, dup_lo = k;

    // ---- tail sums (exact, tie-correct) ----
    float ts = 0.f, bs = 0.f;
    for (int i = tid; i < R2; i += 256) {
        unsigned key = su[i];
        if (key > Khi) ts += fast_exp2x(k2f(key));
        if (key < Klo) bs += fast_exp2x(k2f(key));
    }
    ts = blockReduce256(ts, redf);
    bs = blockReduce256(bs, redf);

    if (tid == 0) {
        float top = ts + (float)dup_hi * fast_exp2x(k2f(Khi));
        float bot = bs + (float)dup_lo * fast_exp2x(k2f(Klo));
        double contrib = 0.5 * (double)logf(tot - top - bot);
        if (r < NROW) contrib -= 2.0 * (double)row[NROW + r];   // -log(pos) for this pair
        atomicAdd(&g_acc, contrib);
    }
}

// ---------------- kernel 4: final scalar ----------------
__global__ void k_final(float* __restrict__ out) {
    out[0] = (float)(g_acc / (double)NROW);
}

// ---------------- launch ----------------
extern "C" void kernel_launch(void* const* d_in, const int* in_sizes, int n_in,
                              void* d_out, int out_size) {
    const float* h1 = (const float*)d_in[0];
    const float* h2 = (const float*)d_in[1];
    (void)in_sizes; (void)n_in; (void)out_size;

    cudaFuncSetAttribute(k_gemm, cudaFuncAttributeMaxDynamicSharedMemorySize,
                         NSTAGE * STAGE_B);

    k_normalize<<<R2, 128>>>(h1, h2);
    k_gemm<<<NBLK, 256, NSTAGE * STAGE_B>>>();
    k_select<<<R2, 256>>>();
    k_final<<<1, 1>>>((float*)d_out);
}

// round 9
// speedup vs baseline: 1.5762x; 1.5762x over previous
#include <cuda_runtime.h>
#include <cuda_bf16.h>
#include <cstdint>
#include <cstddef>

#define NROW 4096
#define DIM  512
#define R2   8192          // 2N
#define THR  409           // int(4096 * 0.1)
#define CAP  1024          // compacted candidate capacity (exact fallback if exceeded)

// ---------------- device scratch (no allocations allowed) ----------------
static __device__ __nv_bfloat16 g_Zb[(size_t)R2 * DIM];   // 8 MB normalized rows (bf16)
static __device__ __nv_bfloat16 g_Sb[(size_t)R2 * R2];    // 128 MB Gram matrix (bf16)
static __device__ double g_acc;

// ================= PTX helpers (base ISA only: sm_80+) =================
__device__ __forceinline__ uint32_t smem_u32(const void* p) {
    uint32_t a;
    asm("{ .reg .u64 t; cvta.to.shared.u64 t, %1; cvt.u32.u64 %0, t; }" : "=r"(a) : "l"(p));
    return a;
}
__device__ __forceinline__ void cp_async16(uint32_t saddr, const void* gptr) {
    asm volatile("cp.async.cg.shared.global [%0], [%1], 16;\n" :: "r"(saddr), "l"(gptr));
}
__device__ __forceinline__ void cp_commit() {
    asm volatile("cp.async.commit_group;\n" ::: "memory");
}
template <int N>
__device__ __forceinline__ void cp_wait() {
    asm volatile("cp.async.wait_group %0;\n" :: "n"(N) : "memory");
}
__device__ __forceinline__ void ldm_x4(uint32_t addr, uint32_t& r0, uint32_t& r1,
                                       uint32_t& r2, uint32_t& r3) {
    asm volatile("ldmatrix.sync.aligned.m8n8.x4.shared.b16 {%0,%1,%2,%3}, [%4];\n"
                 : "=r"(r0), "=r"(r1), "=r"(r2), "=r"(r3) : "r"(addr));
}
__device__ __forceinline__ void mma_bf16(float& d0, float& d1, float& d2, float& d3,
                                         uint32_t a0, uint32_t a1, uint32_t a2, uint32_t a3,
                                         uint32_t b0, uint32_t b1) {
    asm volatile("mma.sync.aligned.m16n8k16.row.col.f32.bf16.bf16.f32 "
                 "{%0,%1,%2,%3}, {%4,%5,%6,%7}, {%8,%9}, {%0,%1,%2,%3};\n"
                 : "+f"(d0), "+f"(d1), "+f"(d2), "+f"(d3)
                 : "r"(a0), "r"(a1), "r"(a2), "r"(a3), "r"(b0), "r"(b1));
}

// ---------------- math helpers ----------------
__device__ __forceinline__ float fast_exp2x(float x) {
    float y = x * 2.885390081777927f;       // 2*log2(e)*x
    float n = rintf(y);
    float r = y - n;
    float p = 1.5403530393381609e-4f;
    p = fmaf(p, r, 1.3333558146428443e-3f);
    p = fmaf(p, r, 9.6181291076284772e-3f);
    p = fmaf(p, r, 5.5504108664821580e-2f);
    p = fmaf(p, r, 2.4022650695910071e-1f);
    p = fmaf(p, r, 6.9314718055994531e-1f);
    p = fmaf(p, r, 1.0f);
    int e = (int)n;
    float s = __int_as_float((e + 127) << 23);
    return p * s;
}
// bf16 bits (low 16) -> order-preserving 16-bit key, and back to float
__device__ __forceinline__ unsigned bf2k(unsigned bits) {
    return (bits & 0x8000u) ? (~bits & 0xFFFFu) : (bits | 0x8000u);
}
__device__ __forceinline__ float kval16(unsigned k) {
    unsigned bits = (k & 0x8000u) ? (k ^ 0x8000u) : (~k & 0xFFFFu);
    return __uint_as_float(bits << 16);
}
// monotone linear bin of the value (exact selection needs monotonicity only)
__device__ __forceinline__ int bin_of(float v) {
    int b = __float2int_rd(fmaf(v, 512.0f, 128.0f));   // (v + 0.25) * 512
    return min(255, max(0, b));
}
__device__ __forceinline__ float blockReduce256(float v, float* red8) {
    int tid = threadIdx.x;
    #pragma unroll
    for (int off = 16; off; off >>= 1) v += __shfl_down_sync(0xffffffffu, v, off);
    if ((tid & 31) == 0) red8[tid >> 5] = v;
    __syncthreads();
    if (tid == 0) {
        float t = 0.f;
        #pragma unroll
        for (int w = 0; w < 8; w++) t += red8[w];
        red8[0] = t;
    }
    __syncthreads();
    float r = red8[0];
    __syncthreads();
    return r;
}
// inclusive prefix scan over hist[256] via warp shuffles; total in warpsum[7]
__device__ __forceinline__ unsigned scan256(unsigned h, unsigned* warpsum, int tid) {
    __syncthreads();
    int lane = tid & 31, w = tid >> 5;
    unsigned v = h;
    #pragma unroll
    for (int off = 1; off < 32; off <<= 1) {
        unsigned u = __shfl_up_sync(0xffffffffu, v, off);
        if (lane >= off) v += u;
    }
    if (lane == 31) warpsum[w] = v;
    __syncthreads();
    if (w == 0) {
        unsigned x = (lane < 8) ? warpsum[lane] : 0u;
        #pragma unroll
        for (int off = 1; off < 8; off <<= 1) {
            unsigned u = __shfl_up_sync(0xffffffffu, x, off);
            if (lane >= off) x += u;
        }
        if (lane < 8) warpsum[lane] = x;
    }
    __syncthreads();
    if (w > 0) v += warpsum[w - 1];
    return v;
}

// ---------------- kernel 1: row L2 normalize -> bf16 ----------------
__global__ void k_normalize(const float* __restrict__ h1, const float* __restrict__ h2) {
    int r = blockIdx.x;
    if (r == 0 && threadIdx.x == 0) g_acc = 0.0;   // stream-ordered zero for select's atomics
    const float* src = (r < NROW) ? (h1 + (size_t)r * DIM)
                                  : (h2 + (size_t)(r - NROW) * DIM);
    int tid = threadIdx.x;                 // 128 threads, 4 floats each
    float4 v = ((const float4*)src)[tid];
    float ss = v.x * v.x + v.y * v.y + v.z * v.z + v.w * v.w;
    __shared__ float red[4];
    #pragma unroll
    for (int off = 16; off; off >>= 1) ss += __shfl_down_sync(0xffffffffu, ss, off);
    if ((tid & 31) == 0) red[tid >> 5] = ss;
    __syncthreads();
    if (tid == 0) {
        float t = red[0] + red[1] + red[2] + red[3];
        red[0] = 1.0f / fmaxf(sqrtf(t), 1e-12f);
    }
    __syncthreads();
    float rinv = red[0];
    __nv_bfloat162 p0 = __floats2bfloat162_rn(v.x * rinv, v.y * rinv);
    __nv_bfloat162 p1 = __floats2bfloat162_rn(v.z * rinv, v.w * rinv);
    __nv_bfloat162* dst = (__nv_bfloat162*)(g_Zb + (size_t)r * DIM);
    dst[tid * 2]     = p0;
    dst[tid * 2 + 1] = p1;
}

// ---------------- kernel 2: S = Z Z^T via mma.sync bf16, SYMMETRIC, bf16 out ----------------
#define ROWB     80
#define TILE_AB  10240                 // 128 rows * 80B
#define STAGE_B  20480                 // A + B
#define NSTAGE   3
#define NKT      16                    // 512 / 32
#define NTILE    64
#define NBLK     (NTILE * (NTILE + 1) / 2)   // 2080

__device__ __forceinline__ void load_stage(uint32_t sBase, int stage, int kt,
                                           int bm, int bn, int tid) {
    const uint32_t st = sBase + stage * STAGE_B;
    const int k0 = kt * 32;
    #pragma unroll
    for (int i = 0; i < 4; i++) {
        int id  = tid + i * 256;           // 0..1023
        int row = (id & 511) >> 2;         // 0..127
        int c   = id & 3;                  // 16B chunk
        int grow = (id < 512) ? (bm + row) : (bn + row);
        const void* g = g_Zb + (size_t)grow * DIM + k0 + c * 8;
        uint32_t s = st + (id < 512 ? 0 : TILE_AB) + row * ROWB + c * 16;
        cp_async16(s, g);
    }
}

__global__ void __launch_bounds__(256, 2) k_gemm() {
    extern __shared__ char dsm[];
    const int tid = threadIdx.x;
    const int wid = tid >> 5, l = tid & 31;

    // triangular decode: t -> (bx >= by)
    int t = blockIdx.x;
    int bx = (int)((sqrtf(8.0f * (float)t + 1.0f) - 1.0f) * 0.5f);
    while ((bx + 1) * (bx + 2) / 2 <= t) bx++;
    while (bx * (bx + 1) / 2 > t) bx--;
    int by = t - bx * (bx + 1) / 2;        // by <= bx
    const int bm = by * 128;               // row tile
    const int bn = bx * 128;               // col tile (>= row tile)

    const int wm = (wid & 3) * 32;
    const int wn = (wid >> 2) * 64;
    const uint32_t sBase = smem_u32(dsm);

    float acc[2][8][4];
    #pragma unroll
    for (int mi = 0; mi < 2; mi++)
        #pragma unroll
        for (int ni = 0; ni < 8; ni++)
            #pragma unroll
            for (int q = 0; q < 4; q++) acc[mi][ni][q] = 0.f;

    load_stage(sBase, 0, 0, bm, bn, tid); cp_commit();
    load_stage(sBase, 1, 1, bm, bn, tid); cp_commit();

    const uint32_t aRow = (l & 15);
    const uint32_t aChk = (l >> 4);
    const uint32_t bRow = ((l >> 4) & 1) * 8 + (l & 7);
    const uint32_t bChk = (l >> 3) & 1;

    for (int kt = 0; kt < NKT; kt++) {
        if (kt < NKT - 2) cp_wait<1>(); else cp_wait<0>();
        __syncthreads();
        if (kt + 2 < NKT) {
            load_stage(sBase, (kt + 2) % NSTAGE, kt + 2, bm, bn, tid);
            cp_commit();
        }
        const uint32_t aB = sBase + (kt % NSTAGE) * STAGE_B + wm * ROWB;
        const uint32_t bB = sBase + (kt % NSTAGE) * STAGE_B + TILE_AB + wn * ROWB;
        #pragma unroll
        for (int ks = 0; ks < 2; ks++) {
            uint32_t a[2][4];
            #pragma unroll
            for (int mi = 0; mi < 2; mi++)
                ldm_x4(aB + (mi * 16 + aRow) * ROWB + (ks * 2 + aChk) * 16,
                       a[mi][0], a[mi][1], a[mi][2], a[mi][3]);
            uint32_t b[4][4];
            #pragma unroll
            for (int nj = 0; nj < 4; nj++)
                ldm_x4(bB + (nj * 16 + bRow) * ROWB + (ks * 2 + bChk) * 16,
                       b[nj][0], b[nj][1], b[nj][2], b[nj][3]);
            #pragma unroll
            for (int mi = 0; mi < 2; mi++)
                #pragma unroll
                for (int ni = 0; ni < 8; ni++)
                    mma_bf16(acc[mi][ni][0], acc[mi][ni][1], acc[mi][ni][2], acc[mi][ni][3],
                             a[mi][0], a[mi][1], a[mi][2], a[mi][3],
                             b[ni >> 1][(ni & 1) * 2], b[ni >> 1][(ni & 1) * 2 + 1]);
        }
        __syncthreads();
    }

    const int r0 = bm + wm + (l >> 2);
    const int c0 = bn + wn + (l & 3) * 2;
    // direct write (bf16 pairs; sectors completed by neighboring ni via L2 write-combine)
    #pragma unroll
    for (int mi = 0; mi < 2; mi++) {
        #pragma unroll
        for (int ni = 0; ni < 8; ni++) {
            __nv_bfloat162 v01 = __floats2bfloat162_rn(acc[mi][ni][0], acc[mi][ni][1]);
            __nv_bfloat162 v23 = __floats2bfloat162_rn(acc[mi][ni][2], acc[mi][ni][3]);
            *(__nv_bfloat162*)(g_Sb + (size_t)(r0 + mi * 16) * R2 + c0 + ni * 8) = v01;
            *(__nv_bfloat162*)(g_Sb + (size_t)(r0 + mi * 16 + 8) * R2 + c0 + ni * 8) = v23;
        }
    }
    // mirror write (2B scattered; lanes sharing l&3 + q pairs complete 32B sectors)
    if (bx != by) {
        #pragma unroll
        for (int mi = 0; mi < 2; mi++) {
            int rA = r0 + mi * 16;
            #pragma unroll
            for (int ni = 0; ni < 8; ni++) {
                int cA = c0 + ni * 8;
                g_Sb[(size_t)cA       * R2 + rA    ] = __float2bfloat16_rn(acc[mi][ni][0]);
                g_Sb[(size_t)(cA + 1) * R2 + rA    ] = __float2bfloat16_rn(acc[mi][ni][1]);
                g_Sb[(size_t)cA       * R2 + rA + 8] = __float2bfloat16_rn(acc[mi][ni][2]);
                g_Sb[(size_t)(cA + 1) * R2 + rA + 8] = __float2bfloat16_rn(acc[mi][ni][3]);
            }
        }
    }
}

// ---------------- kernel 3: per-row trim + exp-sum (linear bins + 16-bit refine) ----------------
__global__ void __launch_bounds__(256) k_select() {
    const int r   = blockIdx.x;
    const int tid = threadIdx.x;
    __shared__ unsigned short su[R2];     // 16 KB: 16-bit order keys
    __shared__ unsigned hist[256];
    __shared__ unsigned short listH[CAP], listL[CAP];
    __shared__ unsigned cntH, cntL;
    __shared__ float    redf[8];
    __shared__ unsigned warpsum[8];
    __shared__ unsigned s_binH, s_kH, s_binL, s_kL, s_sel, s_k;

    const uint4* row4 = (const uint4*)(g_Sb + (size_t)r * R2);   // 1024 uint4

    if (tid == 0) { cntH = 0u; cntL = 0u; }
    hist[tid] = 0u;
    __syncthreads();

    // sweep 1: load bf16, exp-sum, keys to smem, linear-bin histogram
    float tot = 0.f;
    #pragma unroll
    for (int j = 0; j < 4; j++) {
        int i4 = tid + j * 256;                  // uint4 index, 8 bf16 each
        uint4 w = row4[i4];
        unsigned wd[4] = {w.x, w.y, w.z, w.w};
        #pragma unroll
        for (int q = 0; q < 4; q++) {
            unsigned lo = wd[q] & 0xFFFFu, hi = wd[q] >> 16;
            float f0 = __uint_as_float(lo << 16);
            float f1 = __uint_as_float(wd[q] & 0xFFFF0000u);
            tot += fast_exp2x(f0) + fast_exp2x(f1);
            su[i4 * 8 + q * 2 + 0] = (unsigned short)bf2k(lo);
            su[i4 * 8 + q * 2 + 1] = (unsigned short)bf2k(hi);
            atomicAdd(&hist[bin_of(f0)], 1u);
            atomicAdd(&hist[bin_of(f1)], 1u);
        }
    }
    tot = blockReduce256(tot, redf);             // barrier: su + hist complete

    // pass 1: one scan -> boundary bins for both ends
    {
        unsigned h   = hist[tid];
        unsigned pre = scan256(h, warpsum, tid);
        unsigned total = warpsum[7];             // = R2
        unsigned ge = total - pre + h, gt = total - pre;
        if (ge >= THR && gt < THR) { s_binH = (unsigned)tid; s_kH = THR - gt; }
        unsigned le = pre, lt = pre - h;
        if (le >= THR && lt < THR) { s_binL = (unsigned)tid; s_kL = THR - lt; }
    }
    __syncthreads();
    const int binH = (int)s_binH, binL = (int)s_binL;

    // compact boundary-bin candidates (bin recomputed from key: identical monotone map)
    for (int i = tid; i < R2; i += 256) {
        unsigned key = su[i];
        int b = bin_of(kval16(key));
        if (b == binH) { unsigned p = atomicAdd(&cntH, 1u); if (p < CAP) listH[p] = (unsigned short)key; }
        if (b == binL) { unsigned p = atomicAdd(&cntL, 1u); if (p < CAP) listL[p] = (unsigned short)key; }
    }
    __syncthreads();
    const bool fbH = (cntH > CAP), fbL = (cntL > CAP);
    const unsigned nH = fbH ? 0u : cntH, nL = fbL ? 0u : cntL;

    // ---- refine high: k-th largest 16-bit key within binH (2 byte passes) ----
    unsigned Khi, dup_hi;
    {
        unsigned k = s_kH, selHi;
        // pass A: top byte
        __syncthreads(); hist[tid] = 0u; __syncthreads();
        if (!fbH) {
            for (unsigned i = tid; i < nH; i += 256) atomicAdd(&hist[listH[i] >> 8], 1u);
        } else {
            for (int i = tid; i < R2; i += 256) {
                unsigned key = su[i];
                if (bin_of(kval16(key)) == binH) atomicAdd(&hist[key >> 8], 1u);
            }
        }
        __syncthreads();
        unsigned h = hist[tid], pre = scan256(h, warpsum, tid);
        unsigned total = warpsum[7];
        unsigned ge = total - pre + h, gt = total - pre;
        if (ge >= k && gt < k) { s_sel = (unsigned)tid; s_k = k - gt; }
        __syncthreads();
        selHi = s_sel; k = s_k;
        // pass B: low byte
        __syncthreads(); hist[tid] = 0u; __syncthreads();
        if (!fbH) {
            for (unsigned i = tid; i < nH; i += 256) {
                unsigned key = listH[i];
                if ((key >> 8) == selHi) atomicAdd(&hist[key & 255u], 1u);
            }
        } else {
            for (int i = tid; i < R2; i += 256) {
                unsigned key = su[i];
                if (bin_of(kval16(key)) == binH && (key >> 8) == selHi)
                    atomicAdd(&hist[key & 255u], 1u);
            }
        }
        __syncthreads();
        h = hist[tid]; pre = scan256(h, warpsum, tid);
        total = warpsum[7];
        ge = total - pre + h; gt = total - pre;
        if (ge >= k && gt < k) { s_sel = (unsigned)tid; s_k = k - gt; }
        __syncthreads();
        Khi = (selHi << 8) | s_sel;
        dup_hi = s_k;
    }

    // ---- refine low: k-th smallest 16-bit key within binL ----
    unsigned Klo, dup_lo;
    {
        unsigned k = s_kL, selLo;
        __syncthreads(); hist[tid] = 0u; __syncthreads();
        if (!fbL) {
            for (unsigned i = tid; i < nL; i += 256) atomicAdd(&hist[listL[i] >> 8], 1u);
        } else {
            for (int i = tid; i < R2; i += 256) {
                unsigned key = su[i];
                if (bin_of(kval16(key)) == binL) atomicAdd(&hist[key >> 8], 1u);
            }
        }
        __syncthreads();
        unsigned h = hist[tid], pre = scan256(h, warpsum, tid);
        unsigned le = pre, lt = pre - h;
        if (le >= k && lt < k) { s_sel = (unsigned)tid; s_k = k - lt; }
        __syncthreads();
        selLo = s_sel; k = s_k;
        __syncthreads(); hist[tid] = 0u; __syncthreads();
        if (!fbL) {
            for (unsigned i = tid; i < nL; i += 256) {
                unsigned key = listL[i];
                if ((key >> 8) == selLo) atomicAdd(&hist[key & 255u], 1u);
            }
        } else {
            for (int i = tid; i < R2; i += 256) {
                unsigned key = su[i];
                if (bin_of(kval16(key)) == binL && (key >> 8) == selLo)
                    atomicAdd(&hist[key & 255u], 1u);
            }
        }
        __syncthreads();
        h = hist[tid]; pre = scan256(h, warpsum, tid);
        le = pre; lt = pre - h;                        // reassign (fix R8 redeclaration)
        if (le >= k && lt < k) { s_sel = (unsigned)tid; s_k = k - lt; }
        __syncthreads();
        Klo = (selLo << 8) | s_sel;
        dup_lo = s_k;
    }

    // ---- tail sums (exact, tie-correct) ----
    float ts = 0.f, bs = 0.f;
    for (int i = tid; i < R2; i += 256) {
        unsigned key = su[i];
        if (key > Khi) ts += fast_exp2x(kval16(key));
        if (key < Klo) bs += fast_exp2x(kval16(key));
    }
    ts = blockReduce256(ts, redf);
    bs = blockReduce256(bs, redf);

    if (tid == 0) {
        float top = ts + (float)dup_hi * fast_exp2x(kval16(Khi));
        float bot = bs + (float)dup_lo * fast_exp2x(kval16(Klo));
        double contrib = 0.5 * (double)logf(tot - top - bot);
        if (r < NROW) {
            float pos = __bfloat162float(g_Sb[(size_t)r * R2 + NROW + r]);
            contrib -= 2.0 * (double)pos;        // -log(pos) for this pair
        }
        atomicAdd(&g_acc, contrib);
    }
}

// ---------------- kernel 4: final scalar ----------------
__global__ void k_final(float* __restrict__ out) {
    out[0] = (float)(g_acc / (double)NROW);
}

// ---------------- launch ----------------
extern "C" void kernel_launch(void* const* d_in, const int* in_sizes, int n_in,
                              void* d_out, int out_size) {
    const float* h1 = (const float*)d_in[0];
    const float* h2 = (const float*)d_in[1];
    (void)in_sizes; (void)n_in; (void)out_size;

    cudaFuncSetAttribute(k_gemm, cudaFuncAttributeMaxDynamicSharedMemorySize,
                         NSTAGE * STAGE_B);

    k_normalize<<<R2, 128>>>(h1, h2);
    k_gemm<<<NBLK, 256, NSTAGE * STAGE_B>>>();
    k_select<<<R2, 256>>>();
    k_final<<<1, 1>>>((float*)d_out);
}